// round 9
// baseline (speedup 1.0000x reference)
#include <cuda_runtime.h>
#include <cuda_fp16.h>
#include <cstdint>
#include <math.h>

#define FD 512
#define RD 196
#define VDIM 300
#define NI 1000
#define NIPAD 1024
#define NB 256

// ---- smem byte map (identical MMA addressing to round 8) ----
#define G1_STAGE 56320
#define G1_QH 0
#define G1_QL 10240
#define G1_BH 20480
#define G1_BL 38400
#define P_H   0
#define PSTR  464
#define G2_BASE  118784
#define G2_STAGE 8704
#define G2_PITCH 272
#define RED_M 153600
#define RED_S 155648
#define INV_S 157696
#define MBAR0 158208
#define MBAR1 158216
#define SMEM_REQ 158720

// ---- global image scratch (prep kernels write final smem images) ----
// qimg: [8 i-tiles][16 chunks][hi 128x40h | lo 128x40h]  (halves)
__device__ __align__(16) __half g_qimg[1310720];
// bimg: [256 b][16 chunks][hi 224x40h | lo 224x40h]
__device__ __align__(16) __half g_bimg[73400320];
// b2img: [256 b][28 stages][32 rows x 136h]  (hi only)
__device__ __align__(16) __half g_b2img[31195136];

// ---------------- PTX helpers ----------------
__device__ __forceinline__ uint32_t smem_u32(const void* p) {
    uint32_t a;
    asm("{ .reg .u64 t; cvta.to.shared.u64 t, %1; cvt.u32.u64 %0, t; }" : "=r"(a) : "l"(p));
    return a;
}
#define MBAR_INIT(mb, c) asm volatile("mbarrier.init.shared.b64 [%0], %1;" :: "r"(mb), "r"(c) : "memory")
#define EXPECT_TX(mb, bytes) \
    asm volatile("mbarrier.arrive.expect_tx.shared.b64 _, [%0], %1;" :: "r"(mb), "r"(bytes) : "memory")
#define BULK_G2S(dst, src, bytes, mb) \
    asm volatile("cp.async.bulk.shared::cluster.global.mbarrier::complete_tx::bytes [%0], [%1], %2, [%3];" \
        :: "r"(dst), "l"(src), "r"(bytes), "r"(mb) : "memory")
#define MBAR_WAIT(mb, par) do {                                               \
    uint32_t _m = (mb), _p = (par), _d;                                       \
    asm volatile("{.reg .pred p; mbarrier.try_wait.parity.acquire.cta.shared::cta.b64 p,[%1],%2; selp.b32 %0,1,0,p;}" \
        : "=r"(_d) : "r"(_m), "r"(_p) : "memory");                            \
    if (!_d) {                                                                \
        asm volatile("{.reg .pred P1; WL_%=: mbarrier.try_wait.parity.acquire.cta.shared::cta.b64 P1,[%0],%1,0x989680;" \
                     " @P1 bra.uni WD_%=; bra.uni WL_%=; WD_%=:}"             \
                     :: "r"(_m), "r"(_p) : "memory");                         \
    }                                                                         \
} while (0)

__device__ __forceinline__ void ldsm4(uint32_t* r, uint32_t a) {
    asm volatile("ldmatrix.sync.aligned.m8n8.x4.shared.b16 {%0,%1,%2,%3},[%4];"
        : "=r"(r[0]), "=r"(r[1]), "=r"(r[2]), "=r"(r[3]) : "r"(a));
}
__device__ __forceinline__ void ldsm4t(uint32_t* r, uint32_t a) {
    asm volatile("ldmatrix.sync.aligned.m8n8.x4.trans.shared.b16 {%0,%1,%2,%3},[%4];"
        : "=r"(r[0]), "=r"(r[1]), "=r"(r[2]), "=r"(r[3]) : "r"(a));
}
__device__ __forceinline__ void ldsm2(uint32_t* r, uint32_t a) {
    asm volatile("ldmatrix.sync.aligned.m8n8.x2.shared.b16 {%0,%1},[%2];"
        : "=r"(r[0]), "=r"(r[1]) : "r"(a));
}
__device__ __forceinline__ void mma_f32(float* d, const uint32_t* a, uint32_t b0, uint32_t b1) {
    asm volatile("mma.sync.aligned.m16n8k16.row.col.f32.f16.f16.f32 "
        "{%0,%1,%2,%3},{%4,%5,%6,%7},{%8,%9},{%0,%1,%2,%3};"
        : "+f"(d[0]), "+f"(d[1]), "+f"(d[2]), "+f"(d[3])
        : "r"(a[0]), "r"(a[1]), "r"(a[2]), "r"(a[3]), "r"(b0), "r"(b1));
}
__device__ __forceinline__ void mma_f16(uint32_t* d, const uint32_t* a, uint32_t b0, uint32_t b1) {
    asm volatile("mma.sync.aligned.m16n8k16.row.col.f16.f16.f16.f16 "
        "{%0,%1},{%2,%3,%4,%5},{%6,%7},{%0,%1};"
        : "+r"(d[0]), "+r"(d[1])
        : "r"(a[0]), "r"(a[1]), "r"(a[2]), "r"(a[3]), "r"(b0), "r"(b1));
}
__device__ __forceinline__ void split16(float v, __half& h, __half& l) {
    h = __float2half_rn(v);
    l = __float2half_rn(v - __half2float(h));
}
__device__ __forceinline__ uint32_t pack2(__half a, __half b) {
    __half2 t = __halves2half2(a, b);
    return *reinterpret_cast<uint32_t*>(&t);
}
__device__ __forceinline__ void addcorr(float* a4, const uint32_t* c2) {
    float2 f0 = __half22float2(*reinterpret_cast<const __half2*>(&c2[0]));
    float2 f1 = __half22float2(*reinterpret_cast<const __half2*>(&c2[1]));
    a4[0] += f0.x; a4[1] += f0.y; a4[2] += f1.x; a4[3] += f1.y;
}

// ---------------- prep 1: q = vecs @ w_g -> qimg (hi/lo, chunked) ----------------
// grid (4, 128): 8 i-rows x 128 f-cols per block
__global__ __launch_bounds__(128) void qgemm16(
    const float* __restrict__ vecs, const float* __restrict__ w_g)
{
    __shared__ float vs[8][VDIM];
    const int f = blockIdx.x * 128 + threadIdx.x;
    const int by = blockIdx.y;
    const int i0 = by * 8;
    for (int e = threadIdx.x; e < 8 * VDIM; e += 128) {
        int ii = e / VDIM, v = e % VDIM, i = i0 + ii;
        vs[ii][v] = (i < NI) ? vecs[i * VDIM + v] : 0.0f;
    }
    __syncthreads();
    float acc[8];
#pragma unroll
    for (int ii = 0; ii < 8; ii++) acc[ii] = 0.0f;
#pragma unroll 4
    for (int v = 0; v < VDIM; v++) {
        float w = w_g[v * FD + f];
#pragma unroll
        for (int ii = 0; ii < 8; ii++) acc[ii] += vs[ii][v] * w;
    }
#pragma unroll
    for (int ii = 0; ii < 8; ii++) {
        __half h, l; split16(acc[ii], h, l);
        size_t o = (size_t)(by >> 4) * 163840 + (size_t)(f >> 5) * 10240
                 + (size_t)((by & 15) * 8 + ii) * 40 + (f & 31);
        g_qimg[o] = h; g_qimg[o + 5120] = l;
    }
}

// ---------------- prep 2: split + transpose H -> bimg + b2img ----------------
// grid (7, 16, 256), block (32, 8)
__global__ __launch_bounds__(256) void hsplit(const float* __restrict__ h)
{
    __shared__ float t[32][33];
    const int b = blockIdx.z, f0 = blockIdx.y * 32, r0 = blockIdx.x * 32;
    const int tx = threadIdx.x, ty = threadIdx.y;
#pragma unroll
    for (int s = 0; s < 4; s++) {
        int fl = ty + 8 * s, r = r0 + tx;
        t[fl][tx] = (r < RD) ? h[((size_t)b * FD + f0 + fl) * RD + r] : 0.0f;
    }
    __syncthreads();
#pragma unroll
    for (int s = 0; s < 4; s++) {
        int rl = ty + 8 * s;
        int f = f0 + tx, r = r0 + rl;
        float v = t[tx][rl];
        __half hi, lo; split16(v, hi, lo);
        // bimg (GEMM1 B image): [b][chunk f>>5][224 rows x 40h], lo at +8960
        size_t ob = (size_t)b * 286720 + (size_t)(f >> 5) * 17920
                  + (size_t)r * 40 + (f & 31);
        g_bimg[ob] = hi; g_bimg[ob + 8960] = lo;
        // b2img (GEMM2 B image): [b][stage q*7+kc][32 rows x 136h], hi only
        size_t o2 = (size_t)b * 121856 + (size_t)((f >> 7) * 7 + (r >> 5)) * 4352
                  + (size_t)(r & 31) * 136 + (f & 127);
        g_b2img[o2] = hi;
    }
}

// ---------------- main fused kernel: 256 threads, 8 warps (2x4) ----------------
__global__ __launch_bounds__(256, 1) void fused_mma(float* __restrict__ out)
{
    extern __shared__ char sm[];
    const uint32_t sbase = smem_u32(sm);
    float* redm = reinterpret_cast<float*>(sm + RED_M);
    float* reds = reinterpret_cast<float*>(sm + RED_S);
    float* invs = reinterpret_cast<float*>(sm + INV_S);

    const int tid = threadIdx.x, lane = tid & 31, wid = tid >> 5;
    const int mw = wid >> 2, nw = wid & 3;
    const int b = blockIdx.y, i0 = blockIdx.x * 128;

    const char* qsrc  = (const char*)g_qimg  + (size_t)blockIdx.x * 327680;
    const char* bsrc  = (const char*)g_bimg  + (size_t)b * 573440;
    const char* b2src = (const char*)g_b2img + (size_t)b * 243712;

    const uint32_t bar[2] = { sbase + MBAR0, sbase + MBAR1 };
    int ph[2] = {0, 0};

    if (tid == 0) { MBAR_INIT(bar[0], 1); MBAR_INIT(bar[1], 1); }
    __syncthreads();

    const int arow = (lane & 7) + ((lane >> 3) & 1) * 8;
    const int acg  = (lane >> 4) * 16;

    // prologue: issue chunks 0,1
    if (tid == 0) {
#pragma unroll
        for (int c0 = 0; c0 < 2; c0++) {
            uint32_t sb = sbase + (uint32_t)c0 * G1_STAGE;
            EXPECT_TX(bar[c0], 56320);
            BULK_G2S(sb,         qsrc + c0 * 20480, 20480u, bar[c0]);
            BULK_G2S(sb + 20480, bsrc + c0 * 35840, 35840u, bar[c0]);
        }
    }

    // ======== GEMM1: C[128 i][224 r], K=512; warp tile 64 x 56 ========
    float acc[4][7][4];
    uint32_t cor[4][7][2];
#pragma unroll
    for (int mf = 0; mf < 4; mf++)
#pragma unroll
        for (int nf = 0; nf < 7; nf++) {
#pragma unroll
            for (int e = 0; e < 4; e++) acc[mf][nf][e] = 0.0f;
            cor[mf][nf][0] = 0u; cor[mf][nf][1] = 0u;
        }

    for (int c = 0; c < 16; c++) {
        const int s = c & 1;
        const uint32_t st = sbase + (uint32_t)s * G1_STAGE;
        MBAR_WAIT(bar[s], ph[s]); ph[s] ^= 1;
#pragma unroll
        for (int kk = 0; kk < 2; kk++) {
            uint32_t ah[4][4], al[4][4];
#pragma unroll
            for (int mf = 0; mf < 4; mf++) {
                uint32_t ad = st + G1_QH + (uint32_t)(mw * 64 + mf * 16 + arow) * 80 + kk * 32 + acg;
                ldsm4(ah[mf], ad);
                ldsm4(al[mf], ad + (G1_QL - G1_QH));
            }
#pragma unroll
            for (int p = 0; p < 3; p++) {
                uint32_t bd = st + G1_BH + (uint32_t)(nw * 56 + p * 16 + arow) * 80 + kk * 32 + acg;
                uint32_t bh[4], bl[4];
                ldsm4(bh, bd);
                ldsm4(bl, bd + (G1_BL - G1_BH));
#pragma unroll
                for (int mf = 0; mf < 4; mf++) {
                    mma_f32(acc[mf][2 * p],     ah[mf], bh[0], bh[2]);
                    mma_f32(acc[mf][2 * p + 1], ah[mf], bh[1], bh[3]);
                    mma_f16(cor[mf][2 * p],     al[mf], bh[0], bh[2]);
                    mma_f16(cor[mf][2 * p + 1], al[mf], bh[1], bh[3]);
                    mma_f16(cor[mf][2 * p],     ah[mf], bl[0], bl[2]);
                    mma_f16(cor[mf][2 * p + 1], ah[mf], bl[1], bl[3]);
                }
            }
            {
                uint32_t bd = st + G1_BH + (uint32_t)(nw * 56 + 48 + (lane & 7)) * 80
                              + kk * 32 + ((lane >> 3) & 1) * 16;
                uint32_t bh[2], bl[2];
                ldsm2(bh, bd);
                ldsm2(bl, bd + (G1_BL - G1_BH));
#pragma unroll
                for (int mf = 0; mf < 4; mf++) {
                    mma_f32(acc[mf][6], ah[mf], bh[0], bh[1]);
                    mma_f16(cor[mf][6], al[mf], bh[0], bh[1]);
                    mma_f16(cor[mf][6], ah[mf], bl[0], bl[1]);
                }
            }
        }
        __syncthreads();
        if (c + 2 < 16 && tid == 0) {
            uint32_t sb = sbase + (uint32_t)s * G1_STAGE;
            EXPECT_TX(bar[s], 56320);
            BULK_G2S(sb,         qsrc + (c + 2) * 20480, 20480u, bar[s]);
            BULK_G2S(sb + 20480, bsrc + (c + 2) * 35840, 35840u, bar[s]);
        }
    }
#pragma unroll
    for (int mf = 0; mf < 4; mf++)
#pragma unroll
        for (int nf = 0; nf < 7; nf++) addcorr(acc[mf][nf], cor[mf][nf]);

    // ======== softmax over r ========
    const int qlane = lane >> 2, plane = 2 * (lane & 3);
#pragma unroll
    for (int mf = 0; mf < 4; mf++)
#pragma unroll
        for (int hh = 0; hh < 2; hh++) {
            float m = -INFINITY;
#pragma unroll
            for (int nf = 0; nf < 7; nf++)
#pragma unroll
                for (int e = 0; e < 2; e++) {
                    int col = nw * 56 + nf * 8 + plane + e;
                    if (col < RD) m = fmaxf(m, acc[mf][nf][2 * hh + e]);
                }
            m = fmaxf(m, __shfl_xor_sync(0xffffffffu, m, 1));
            m = fmaxf(m, __shfl_xor_sync(0xffffffffu, m, 2));
            if ((lane & 3) == 0) {
                int row = mw * 64 + mf * 16 + qlane + hh * 8;
                redm[row * 4 + nw] = m;
            }
        }
    __syncthreads();
#pragma unroll
    for (int mf = 0; mf < 4; mf++)
#pragma unroll
        for (int hh = 0; hh < 2; hh++) {
            int row = mw * 64 + mf * 16 + qlane + hh * 8;
            float m = fmaxf(fmaxf(redm[row * 4], redm[row * 4 + 1]),
                            fmaxf(redm[row * 4 + 2], redm[row * 4 + 3]));
            float s = 0.0f;
#pragma unroll
            for (int nf = 0; nf < 7; nf++) {
                float v0 = 0.0f, v1 = 0.0f;
                int col = nw * 56 + nf * 8 + plane;
                if (col     < RD) { v0 = __expf(acc[mf][nf][2 * hh]     - m); s += v0; }
                if (col + 1 < RD) { v1 = __expf(acc[mf][nf][2 * hh + 1] - m); s += v1; }
                uint32_t off = (uint32_t)row * PSTR + (uint32_t)col * 2;
                *reinterpret_cast<uint32_t*>(sm + P_H + off) =
                    pack2(__float2half_rn(v0), __float2half_rn(v1));
            }
            s += __shfl_xor_sync(0xffffffffu, s, 1);
            s += __shfl_xor_sync(0xffffffffu, s, 2);
            if ((lane & 3) == 0) reds[row * 4 + nw] = s;
        }
    __syncthreads();
    if (wid < 4) {
        int row = wid * 32 + lane;
        float t = reds[row * 4] + reds[row * 4 + 1] + reds[row * 4 + 2] + reds[row * 4 + 3];
        invs[row] = 1.0f / t;
    }
    __syncthreads();

    // GEMM2 prologue: issue stages 0,1
    if (tid == 0) {
#pragma unroll
        for (int t0 = 0; t0 < 2; t0++) {
            EXPECT_TX(bar[t0], 8704);
            BULK_G2S(sbase + G2_BASE + (uint32_t)t0 * G2_STAGE,
                     b2src + t0 * 8704, 8704u, bar[t0]);
        }
    }

    // ======== GEMM2: E[128 i][512 f], K=224; P hi-only, B hi-only ========
    const int brow = lane & 15;
    const int bcg  = (lane >> 4) * 16;
    for (int q = 0; q < 4; q++) {
        float acc2[4][4][4];
#pragma unroll
        for (int mf = 0; mf < 4; mf++)
#pragma unroll
            for (int nf = 0; nf < 4; nf++)
#pragma unroll
                for (int e = 0; e < 4; e++) acc2[mf][nf][e] = 0.0f;

        for (int kc = 0; kc < 7; kc++) {
            const int cur = q * 7 + kc;
            const int s = cur & 1;
            const uint32_t st = sbase + G2_BASE + (uint32_t)s * G2_STAGE;
            MBAR_WAIT(bar[s], ph[s]); ph[s] ^= 1;
#pragma unroll
            for (int kk = 0; kk < 2; kk++) {
                uint32_t ah[4][4];
#pragma unroll
                for (int mf = 0; mf < 4; mf++) {
                    uint32_t ad = sbase + P_H + (uint32_t)(mw * 64 + mf * 16 + arow) * PSTR
                                  + (uint32_t)(kc * 64 + kk * 32) + acg;
                    ldsm4(ah[mf], ad);
                }
#pragma unroll
                for (int p = 0; p < 2; p++) {
                    uint32_t bd = st + (uint32_t)(kk * 16 + brow) * G2_PITCH
                                  + (uint32_t)(nw * 64 + p * 32) + bcg;
                    uint32_t bh[4];
                    ldsm4t(bh, bd);
#pragma unroll
                    for (int mf = 0; mf < 4; mf++) {
                        mma_f32(acc2[mf][2 * p],     ah[mf], bh[0], bh[1]);
                        mma_f32(acc2[mf][2 * p + 1], ah[mf], bh[2], bh[3]);
                    }
                }
            }
            __syncthreads();
            if (cur + 2 < 28 && tid == 0) {
                EXPECT_TX(bar[s], 8704);
                BULK_G2S(sbase + G2_BASE + (uint32_t)s * G2_STAGE,
                         b2src + (cur + 2) * 8704, 8704u, bar[s]);
            }
        }

#pragma unroll
        for (int mf = 0; mf < 4; mf++) {
            int r0 = mw * 64 + mf * 16 + qlane;
            float is0 = invs[r0], is1 = invs[r0 + 8];
            int gi0 = i0 + r0, gi1 = gi0 + 8;
#pragma unroll
            for (int nf = 0; nf < 4; nf++) {
                int f = q * 128 + nw * 32 + nf * 8 + plane;
                if (gi0 < NI) {
                    float2 v = make_float2(acc2[mf][nf][0] * is0, acc2[mf][nf][1] * is0);
                    *reinterpret_cast<float2*>(out + ((size_t)b * NI + gi0) * FD + f) = v;
                }
                if (gi1 < NI) {
                    float2 v = make_float2(acc2[mf][nf][2] * is1, acc2[mf][nf][3] * is1);
                    *reinterpret_cast<float2*>(out + ((size_t)b * NI + gi1) * FD + f) = v;
                }
            }
        }
    }
}

// ---------------------------------------------------------------------------
extern "C" void kernel_launch(void* const* d_in, const int* in_sizes, int n_in,
                              void* d_out, int out_size)
{
    const float* h_r  = (const float*)d_in[0];  // (256, 512, 196)
    const float* vecs = (const float*)d_in[1];  // (1000, 300)
    const float* w_g  = (const float*)d_in[2];  // (300, 512)
    float* out = (float*)d_out;                 // (256, 1000, 512)

    cudaFuncSetAttribute(fused_mma, cudaFuncAttributeMaxDynamicSharedMemorySize, SMEM_REQ);

    qgemm16<<<dim3(4, NIPAD / 8), 128>>>(vecs, w_g);
    hsplit<<<dim3(7, 16, NB), dim3(32, 8)>>>(h_r);
    fused_mma<<<dim3(NIPAD / 128, NB), 256, SMEM_REQ>>>(out);
}

// round 10
// speedup vs baseline: 1.0169x; 1.0169x over previous
#include <cuda_runtime.h>
#include <cuda_fp16.h>
#include <cstdint>
#include <math.h>

#define FD 512
#define RD 196
#define RP 224
#define VDIM 300
#define NI 1000
#define NIPAD 1024
#define NB 256

// ---- smem byte map ----
#define G1_STAGE 28160          // per-stage: QH 128x80B @0, BH 224x80B @10240
#define G1_BH    10240
#define A_OFF    57344          // logits: 128 rows x 228 floats (116736 B)
#define APITCH   228
#define SMEM_REQ 175104

__device__ __align__(16) __half g_qh[NIPAD * FD];
__device__ __align__(16) __half g_ql[NIPAD * FD];
__device__ __align__(16) __half g_th[(size_t)NB * RP * FD];  // Ht [b][r][f] hi
__device__ __align__(16) __half g_tl[(size_t)NB * RP * FD];  // lo

// ---------------- PTX helpers ----------------
__device__ __forceinline__ uint32_t smem_u32(const void* p) {
    uint32_t a;
    asm("{ .reg .u64 t; cvta.to.shared.u64 t, %1; cvt.u32.u64 %0, t; }" : "=r"(a) : "l"(p));
    return a;
}
__device__ __forceinline__ void cpa16(uint32_t d, const void* s) {
    asm volatile("cp.async.cg.shared.global [%0], [%1], 16;" :: "r"(d), "l"(s));
}
#define CP_COMMIT() asm volatile("cp.async.commit_group;")
__device__ __forceinline__ void ldsm4(uint32_t* r, uint32_t a) {
    asm volatile("ldmatrix.sync.aligned.m8n8.x4.shared.b16 {%0,%1,%2,%3},[%4];"
        : "=r"(r[0]), "=r"(r[1]), "=r"(r[2]), "=r"(r[3]) : "r"(a));
}
__device__ __forceinline__ void ldsm2(uint32_t* r, uint32_t a) {
    asm volatile("ldmatrix.sync.aligned.m8n8.x2.shared.b16 {%0,%1},[%2];"
        : "=r"(r[0]), "=r"(r[1]) : "r"(a));
}
__device__ __forceinline__ void mma_f32(float* d, const uint32_t* a, uint32_t b0, uint32_t b1) {
    asm volatile("mma.sync.aligned.m16n8k16.row.col.f32.f16.f16.f32 "
        "{%0,%1,%2,%3},{%4,%5,%6,%7},{%8,%9},{%0,%1,%2,%3};"
        : "+f"(d[0]), "+f"(d[1]), "+f"(d[2]), "+f"(d[3])
        : "r"(a[0]), "r"(a[1]), "r"(a[2]), "r"(a[3]), "r"(b0), "r"(b1));
}
__device__ __forceinline__ void split16(float v, __half& h, __half& l) {
    h = __float2half_rn(v);
    l = __float2half_rn(v - __half2float(h));
}

// ---------------- prep 1: q = vecs @ w_g -> fp16 hi/lo ----------------
__global__ __launch_bounds__(128) void qgemm16(
    const float* __restrict__ vecs, const float* __restrict__ w_g)
{
    __shared__ float vs[8][VDIM];
    const int f = blockIdx.x * 128 + threadIdx.x;
    const int i0 = blockIdx.y * 8;
    for (int e = threadIdx.x; e < 8 * VDIM; e += 128) {
        int ii = e / VDIM, v = e % VDIM, i = i0 + ii;
        vs[ii][v] = (i < NI) ? vecs[i * VDIM + v] : 0.0f;
    }
    __syncthreads();
    float acc[8];
#pragma unroll
    for (int ii = 0; ii < 8; ii++) acc[ii] = 0.0f;
#pragma unroll 4
    for (int v = 0; v < VDIM; v++) {
        float w = w_g[v * FD + f];
#pragma unroll
        for (int ii = 0; ii < 8; ii++) acc[ii] += vs[ii][v] * w;
    }
#pragma unroll
    for (int ii = 0; ii < 8; ii++) {
        __half h, l; split16(acc[ii], h, l);
        size_t o = (size_t)(i0 + ii) * FD + f;
        g_qh[o] = h; g_ql[o] = l;
    }
}

// ---------------- prep 2: split + transpose H -> g_th/g_tl ----------------
__global__ __launch_bounds__(256) void hsplit(const float* __restrict__ h)
{
    __shared__ float t[32][33];
    const int b = blockIdx.z, f0 = blockIdx.y * 32, r0 = blockIdx.x * 32;
    const int tx = threadIdx.x, ty = threadIdx.y;
#pragma unroll
    for (int s = 0; s < 4; s++) {
        int fl = ty + 8 * s, r = r0 + tx;
        t[fl][tx] = (r < RD) ? h[((size_t)b * FD + f0 + fl) * RD + r] : 0.0f;
    }
    __syncthreads();
#pragma unroll
    for (int s = 0; s < 4; s++) {
        int rl = ty + 8 * s;
        float v = t[tx][rl];
        __half hi, lo; split16(v, hi, lo);
        size_t o = ((size_t)b * RP + r0 + rl) * FD + f0 + tx;
        g_th[o] = hi; g_tl[o] = lo;
    }
}

// ---------------- GEMM1 stage loader (hi only) ----------------
__device__ __forceinline__ void issue_g1(uint32_t sb,
    const __half* qh, const __half* th, int c, int tid)
{
    const int ko = c * 32;
    for (int t = tid; t < 512; t += 256) {
        int row = t >> 2, cc = t & 3;
        cpa16(sb + row * 80 + cc * 16, qh + row * FD + ko + cc * 8);
    }
    for (int t = tid; t < 896; t += 256) {
        int row = t >> 2, cc = t & 3;
        cpa16(sb + G1_BH + row * 80 + cc * 16, th + row * FD + ko + cc * 8);
    }
}

// ---------------- main fused kernel: 256 threads, 8 warps (2x4) ----------------
__global__ __launch_bounds__(256, 1) void fused_mma(float* __restrict__ out)
{
    extern __shared__ char sm[];
    const uint32_t sbase = smem_u32(sm);
    float* A = reinterpret_cast<float*>(sm + A_OFF);

    const int tid = threadIdx.x, lane = tid & 31, wid = tid >> 5;
    const int mw = wid >> 2, nw = wid & 3;
    const int b = blockIdx.y, i0 = blockIdx.x * 128;

    const __half* qh = g_qh + (size_t)i0 * FD;
    const __half* th = g_th + (size_t)b * RP * FD;
    const __half* tl = g_tl + (size_t)b * RP * FD;

    const int arow = (lane & 7) + ((lane >> 3) & 1) * 8;
    const int acg  = (lane >> 4) * 16;

    // ======== GEMM1 (hi only): C[128 i][224 r], K=512; warp tile 64x56 ========
    float acc[4][7][4];
#pragma unroll
    for (int mf = 0; mf < 4; mf++)
#pragma unroll
        for (int nf = 0; nf < 7; nf++)
#pragma unroll
            for (int e = 0; e < 4; e++) acc[mf][nf][e] = 0.0f;

    issue_g1(sbase, qh, th, 0, tid);
    CP_COMMIT();
    for (int c = 0; c < 16; c++) {
        const uint32_t st = sbase + (uint32_t)(c & 1) * G1_STAGE;
        if (c < 15) {
            issue_g1(sbase + (uint32_t)((c + 1) & 1) * G1_STAGE, qh, th, c + 1, tid);
            CP_COMMIT();
            asm volatile("cp.async.wait_group 1;");
        } else {
            asm volatile("cp.async.wait_group 0;");
        }
        __syncthreads();
#pragma unroll
        for (int kk = 0; kk < 2; kk++) {
            uint32_t ah[4][4];
#pragma unroll
            for (int mf = 0; mf < 4; mf++) {
                uint32_t ad = st + (uint32_t)(mw * 64 + mf * 16 + arow) * 80 + kk * 32 + acg;
                ldsm4(ah[mf], ad);
            }
#pragma unroll
            for (int p = 0; p < 3; p++) {
                uint32_t bd = st + G1_BH + (uint32_t)(nw * 56 + p * 16 + arow) * 80 + kk * 32 + acg;
                uint32_t bh[4];
                ldsm4(bh, bd);
#pragma unroll
                for (int mf = 0; mf < 4; mf++) {
                    mma_f32(acc[mf][2 * p],     ah[mf], bh[0], bh[2]);
                    mma_f32(acc[mf][2 * p + 1], ah[mf], bh[1], bh[3]);
                }
            }
            {
                uint32_t bd = st + G1_BH + (uint32_t)(nw * 56 + 48 + (lane & 7)) * 80
                              + kk * 32 + ((lane >> 3) & 1) * 16;
                uint32_t bh[2];
                ldsm2(bh, bd);
#pragma unroll
                for (int mf = 0; mf < 4; mf++)
                    mma_f32(acc[mf][6], ah[mf], bh[0], bh[1]);
            }
        }
        __syncthreads();
    }

    // write approx logits to smem A [128][APITCH]
    const int qlane = lane >> 2, plane = 2 * (lane & 3);
#pragma unroll
    for (int mf = 0; mf < 4; mf++) {
        int row0 = mw * 64 + mf * 16 + qlane;
#pragma unroll
        for (int nf = 0; nf < 7; nf++) {
            int col = nw * 56 + nf * 8 + plane;
            *reinterpret_cast<float2*>(A + row0 * APITCH + col) =
                make_float2(acc[mf][nf][0], acc[mf][nf][1]);
            *reinterpret_cast<float2*>(A + (row0 + 8) * APITCH + col) =
                make_float2(acc[mf][nf][2], acc[mf][nf][3]);
        }
    }
    __syncthreads();

    // ======== per-row: candidates -> exact logits -> softmax -> e_g gather ========
    for (int tt = 0; tt < 16; tt++) {
        const int row = wid * 16 + tt;
        const int i = i0 + row;
        if (i >= NI) continue;
        float* Ar = A + row * APITCH;

        float a[7];
#pragma unroll
        for (int j = 0; j < 7; j++) a[j] = Ar[lane + 32 * j];
        if (lane >= 4) a[6] = -1e30f;   // mask cols 196..223

        float M = a[0];
#pragma unroll
        for (int j = 1; j < 7; j++) M = fmaxf(M, a[j]);
#pragma unroll
        for (int o = 16; o > 0; o >>= 1) M = fmaxf(M, __shfl_xor_sync(0xffffffffu, M, o));

        const float thr = M - 30.0f;
        uint32_t bits[7];
#pragma unroll
        for (int j = 0; j < 7; j++) bits[j] = __ballot_sync(0xffffffffu, a[j] > thr);

        // pass 1: exact fp32 logits for candidates; online max/sum
        const __half2* qh2 = reinterpret_cast<const __half2*>(g_qh + (size_t)i * FD);
        const __half2* ql2 = reinterpret_cast<const __half2*>(g_ql + (size_t)i * FD);
        float m = -INFINITY, ssum = 0.0f;
#pragma unroll 1
        for (int j = 0; j < 7; j++) {
            uint32_t bs = bits[j];
            while (bs) {
                int c = j * 32 + __ffs(bs) - 1; bs &= bs - 1;
                const __half2* hh2 = reinterpret_cast<const __half2*>(th + (size_t)c * FD);
                const __half2* hl2 = reinterpret_cast<const __half2*>(tl + (size_t)c * FD);
                float s = 0.0f;
#pragma unroll
                for (int k = 0; k < 8; k++) {
                    int idx = lane + 32 * k;
                    float2 qa = __half22float2(qh2[idx]);
                    float2 qb = __half22float2(ql2[idx]);
                    float2 ha = __half22float2(hh2[idx]);
                    float2 hb = __half22float2(hl2[idx]);
                    s += (qa.x + qb.x) * (ha.x + hb.x) + (qa.y + qb.y) * (ha.y + hb.y);
                }
#pragma unroll
                for (int o = 16; o > 0; o >>= 1) s += __shfl_xor_sync(0xffffffffu, s, o);
                if (lane == 0) Ar[c] = s;
                float mn = fmaxf(m, s);
                ssum = ssum * __expf(m - mn) + __expf(s - mn);
                m = mn;
            }
        }
        __syncwarp();
        const float inv = 1.0f / ssum;

        // pass 2: e_g[i,:] = sum_cand p_c * h[c,:]
        float2 eg[8];
#pragma unroll
        for (int k = 0; k < 8; k++) eg[k] = make_float2(0.0f, 0.0f);
#pragma unroll 1
        for (int j = 0; j < 7; j++) {
            uint32_t bs = bits[j];
            while (bs) {
                int c = j * 32 + __ffs(bs) - 1; bs &= bs - 1;
                float wgt = __expf(Ar[c] - m) * inv;
                const __half2* hh2 = reinterpret_cast<const __half2*>(th + (size_t)c * FD);
                const __half2* hl2 = reinterpret_cast<const __half2*>(tl + (size_t)c * FD);
#pragma unroll
                for (int k = 0; k < 8; k++) {
                    int idx = lane + 32 * k;
                    float2 ha = __half22float2(hh2[idx]);
                    float2 hb = __half22float2(hl2[idx]);
                    eg[k].x += wgt * (ha.x + hb.x);
                    eg[k].y += wgt * (ha.y + hb.y);
                }
            }
        }
        float2* op = reinterpret_cast<float2*>(out + ((size_t)b * NI + i) * FD);
#pragma unroll
        for (int k = 0; k < 8; k++) op[lane + 32 * k] = eg[k];
    }
}

// ---------------------------------------------------------------------------
extern "C" void kernel_launch(void* const* d_in, const int* in_sizes, int n_in,
                              void* d_out, int out_size)
{
    const float* h_r  = (const float*)d_in[0];  // (256, 512, 196)
    const float* vecs = (const float*)d_in[1];  // (1000, 300)
    const float* w_g  = (const float*)d_in[2];  // (300, 512)
    float* out = (float*)d_out;                 // (256, 1000, 512)

    cudaFuncSetAttribute(fused_mma, cudaFuncAttributeMaxDynamicSharedMemorySize, SMEM_REQ);

    qgemm16<<<dim3(4, NIPAD / 8), 128>>>(vecs, w_g);
    hsplit<<<dim3(7, 16, NB), dim3(32, 8)>>>(h_r);
    fused_mma<<<dim3(NIPAD / 128, NB), 256, SMEM_REQ>>>(out);
}

// round 11
// speedup vs baseline: 1.3996x; 1.3764x over previous
#include <cuda_runtime.h>
#include <cuda_fp16.h>
#include <cstdint>
#include <math.h>

#define FD 512
#define RD 196
#define RP 224
#define VDIM 300
#define NI 1000
#define NIPAD 1024
#define NB 256

// ---- smem byte map ----
#define G1_STAGE 28160          // per-stage: QH 128x80B @0, BH 224x80B @10240
#define G1_BH    10240
#define A_OFF    57344          // logits: 128 rows x 228 floats
#define APITCH   228
#define SMEM_REQ 175104

__device__ __align__(16) __half g_qh[NIPAD * FD];                 // q hi (GEMM1 A)
__device__ __align__(16) float  g_q32[NIPAD * FD];                // q fp32 (exact dot)
__device__ __align__(16) __half g_th[(size_t)NB * RP * FD];       // Ht hi [b][r][f] (GEMM1 B)
__device__ __align__(16) float  g_tf[(size_t)NB * RP * FD];       // Ht fp32 [b][r][f] (gather)

// ---------------- PTX helpers ----------------
__device__ __forceinline__ uint32_t smem_u32(const void* p) {
    uint32_t a;
    asm("{ .reg .u64 t; cvta.to.shared.u64 t, %1; cvt.u32.u64 %0, t; }" : "=r"(a) : "l"(p));
    return a;
}
__device__ __forceinline__ void cpa16(uint32_t d, const void* s) {
    asm volatile("cp.async.cg.shared.global [%0], [%1], 16;" :: "r"(d), "l"(s));
}
#define CP_COMMIT() asm volatile("cp.async.commit_group;")
__device__ __forceinline__ void ldsm4(uint32_t* r, uint32_t a) {
    asm volatile("ldmatrix.sync.aligned.m8n8.x4.shared.b16 {%0,%1,%2,%3},[%4];"
        : "=r"(r[0]), "=r"(r[1]), "=r"(r[2]), "=r"(r[3]) : "r"(a));
}
__device__ __forceinline__ void ldsm2(uint32_t* r, uint32_t a) {
    asm volatile("ldmatrix.sync.aligned.m8n8.x2.shared.b16 {%0,%1},[%2];"
        : "=r"(r[0]), "=r"(r[1]) : "r"(a));
}
__device__ __forceinline__ void mma_f32(float* d, const uint32_t* a, uint32_t b0, uint32_t b1) {
    asm volatile("mma.sync.aligned.m16n8k16.row.col.f32.f16.f16.f32 "
        "{%0,%1,%2,%3},{%4,%5,%6,%7},{%8,%9},{%0,%1,%2,%3};"
        : "+f"(d[0]), "+f"(d[1]), "+f"(d[2]), "+f"(d[3])
        : "r"(a[0]), "r"(a[1]), "r"(a[2]), "r"(a[3]), "r"(b0), "r"(b1));
}

// ---------------- prep 1: q = vecs @ w_g -> fp16 hi + fp32 ----------------
__global__ __launch_bounds__(128) void qgemm16(
    const float* __restrict__ vecs, const float* __restrict__ w_g)
{
    __shared__ float vs[8][VDIM];
    const int f = blockIdx.x * 128 + threadIdx.x;
    const int i0 = blockIdx.y * 8;
    for (int e = threadIdx.x; e < 8 * VDIM; e += 128) {
        int ii = e / VDIM, v = e % VDIM, i = i0 + ii;
        vs[ii][v] = (i < NI) ? vecs[i * VDIM + v] : 0.0f;
    }
    __syncthreads();
    float acc[8];
#pragma unroll
    for (int ii = 0; ii < 8; ii++) acc[ii] = 0.0f;
#pragma unroll 4
    for (int v = 0; v < VDIM; v++) {
        float w = w_g[v * FD + f];
#pragma unroll
        for (int ii = 0; ii < 8; ii++) acc[ii] += vs[ii][v] * w;
    }
#pragma unroll
    for (int ii = 0; ii < 8; ii++) {
        size_t o = (size_t)(i0 + ii) * FD + f;
        g_qh[o] = __float2half_rn(acc[ii]);
        g_q32[o] = acc[ii];
    }
}

// ---------------- prep 2: transpose H -> g_th (hi) + g_tf (fp32) ----------------
__global__ __launch_bounds__(256) void hsplit(const float* __restrict__ h)
{
    __shared__ float t[32][33];
    const int b = blockIdx.z, f0 = blockIdx.y * 32, r0 = blockIdx.x * 32;
    const int tx = threadIdx.x, ty = threadIdx.y;
#pragma unroll
    for (int s = 0; s < 4; s++) {
        int fl = ty + 8 * s, r = r0 + tx;
        t[fl][tx] = (r < RD) ? h[((size_t)b * FD + f0 + fl) * RD + r] : 0.0f;
    }
    __syncthreads();
#pragma unroll
    for (int s = 0; s < 4; s++) {
        int rl = ty + 8 * s;
        float v = t[tx][rl];
        size_t o = ((size_t)b * RP + r0 + rl) * FD + f0 + tx;
        g_th[o] = __float2half_rn(v);
        g_tf[o] = v;
    }
}

// ---------------- GEMM1 stage loader (hi only) ----------------
__device__ __forceinline__ void issue_g1(uint32_t sb,
    const __half* qh, const __half* th, int c, int tid)
{
    const int ko = c * 32;
    for (int t = tid; t < 512; t += 256) {
        int row = t >> 2, cc = t & 3;
        cpa16(sb + row * 80 + cc * 16, qh + row * FD + ko + cc * 8);
    }
    for (int t = tid; t < 896; t += 256) {
        int row = t >> 2, cc = t & 3;
        cpa16(sb + G1_BH + row * 80 + cc * 16, th + row * FD + ko + cc * 8);
    }
}

// ---------------- main fused kernel: 256 threads, 8 warps (2x4) ----------------
__global__ __launch_bounds__(256, 1) void fused_mma(float* __restrict__ out)
{
    extern __shared__ char sm[];
    const uint32_t sbase = smem_u32(sm);
    float* A = reinterpret_cast<float*>(sm + A_OFF);

    const int tid = threadIdx.x, lane = tid & 31, wid = tid >> 5;
    const int mw = wid >> 2, nw = wid & 3;
    const int b = blockIdx.y, i0 = blockIdx.x * 128;

    const __half* qh = g_qh + (size_t)i0 * FD;
    const __half* th = g_th + (size_t)b * RP * FD;

    const int arow = (lane & 7) + ((lane >> 3) & 1) * 8;
    const int acg  = (lane >> 4) * 16;

    // ======== GEMM1 (hi only): C[128 i][224 r], K=512; warp tile 64x56 ========
    float acc[4][7][4];
#pragma unroll
    for (int mf = 0; mf < 4; mf++)
#pragma unroll
        for (int nf = 0; nf < 7; nf++)
#pragma unroll
            for (int e = 0; e < 4; e++) acc[mf][nf][e] = 0.0f;

    issue_g1(sbase, qh, th, 0, tid);
    CP_COMMIT();
    for (int c = 0; c < 16; c++) {
        const uint32_t st = sbase + (uint32_t)(c & 1) * G1_STAGE;
        if (c < 15) {
            issue_g1(sbase + (uint32_t)((c + 1) & 1) * G1_STAGE, qh, th, c + 1, tid);
            CP_COMMIT();
            asm volatile("cp.async.wait_group 1;");
        } else {
            asm volatile("cp.async.wait_group 0;");
        }
        __syncthreads();
#pragma unroll
        for (int kk = 0; kk < 2; kk++) {
            uint32_t ah[4][4];
#pragma unroll
            for (int mf = 0; mf < 4; mf++) {
                uint32_t ad = st + (uint32_t)(mw * 64 + mf * 16 + arow) * 80 + kk * 32 + acg;
                ldsm4(ah[mf], ad);
            }
#pragma unroll
            for (int p = 0; p < 3; p++) {
                uint32_t bd = st + G1_BH + (uint32_t)(nw * 56 + p * 16 + arow) * 80 + kk * 32 + acg;
                uint32_t bh[4];
                ldsm4(bh, bd);
#pragma unroll
                for (int mf = 0; mf < 4; mf++) {
                    mma_f32(acc[mf][2 * p],     ah[mf], bh[0], bh[2]);
                    mma_f32(acc[mf][2 * p + 1], ah[mf], bh[1], bh[3]);
                }
            }
            {
                uint32_t bd = st + G1_BH + (uint32_t)(nw * 56 + 48 + (lane & 7)) * 80
                              + kk * 32 + ((lane >> 3) & 1) * 16;
                uint32_t bh[2];
                ldsm2(bh, bd);
#pragma unroll
                for (int mf = 0; mf < 4; mf++)
                    mma_f32(acc[mf][6], ah[mf], bh[0], bh[1]);
            }
        }
        __syncthreads();
    }

    // write approx logits to smem A [128][APITCH]
    const int qlane = lane >> 2, plane = 2 * (lane & 3);
#pragma unroll
    for (int mf = 0; mf < 4; mf++) {
        int row0 = mw * 64 + mf * 16 + qlane;
#pragma unroll
        for (int nf = 0; nf < 7; nf++) {
            int col = nw * 56 + nf * 8 + plane;
            *reinterpret_cast<float2*>(A + row0 * APITCH + col) =
                make_float2(acc[mf][nf][0], acc[mf][nf][1]);
            *reinterpret_cast<float2*>(A + (row0 + 8) * APITCH + col) =
                make_float2(acc[mf][nf][2], acc[mf][nf][3]);
        }
    }
    __syncthreads();

    // ======== per-row: candidates -> exact fp32 logits -> online softmax-gather ========
    for (int tt = 0; tt < 16; tt++) {
        const int row = wid * 16 + tt;
        const int i = i0 + row;
        if (i >= NI) continue;
        float* Ar = A + row * APITCH;

        float a[7];
#pragma unroll
        for (int j = 0; j < 7; j++) a[j] = Ar[lane + 32 * j];
        if (lane >= 4) a[6] = -1e30f;   // mask cols 196..223

        float M = a[0];
#pragma unroll
        for (int j = 1; j < 7; j++) M = fmaxf(M, a[j]);
#pragma unroll
        for (int o = 16; o > 0; o >>= 1) M = fmaxf(M, __shfl_xor_sync(0xffffffffu, M, o));

        const float thr = M - 22.0f;
        uint32_t bits[7];
#pragma unroll
        for (int j = 0; j < 7; j++) bits[j] = __ballot_sync(0xffffffffu, a[j] > thr);

        // q row (fp32), resident across candidates
        const float* q32 = g_q32 + (size_t)i * FD;
        float qr[16];
#pragma unroll
        for (int k = 0; k < 16; k++) qr[k] = q32[lane + 32 * k];

        float m = -INFINITY, ssum = 0.0f;
        float eg[16];
#pragma unroll
        for (int k = 0; k < 16; k++) eg[k] = 0.0f;

#pragma unroll 1
        for (int j = 0; j < 7; j++) {
            uint32_t bs = bits[j];
            while (bs) {
                int c = j * 32 + __ffs(bs) - 1; bs &= bs - 1;
                const float* hp = g_tf + ((size_t)b * RP + c) * FD;
                float hr[16];
#pragma unroll
                for (int k = 0; k < 16; k++) hr[k] = hp[lane + 32 * k];
                float s = 0.0f;
#pragma unroll
                for (int k = 0; k < 16; k++) s += qr[k] * hr[k];
#pragma unroll
                for (int o = 16; o > 0; o >>= 1) s += __shfl_xor_sync(0xffffffffu, s, o);
                float mn = fmaxf(m, s);
                float sc = __expf(m - mn);
                float w  = __expf(s - mn);
                ssum = ssum * sc + w;
#pragma unroll
                for (int k = 0; k < 16; k++) eg[k] = eg[k] * sc + w * hr[k];
                m = mn;
            }
        }
        const float inv = 1.0f / ssum;
        float* op = out + ((size_t)b * NI + i) * FD;
#pragma unroll
        for (int k = 0; k < 16; k++) op[lane + 32 * k] = eg[k] * inv;
    }
}

// ---------------------------------------------------------------------------
extern "C" void kernel_launch(void* const* d_in, const int* in_sizes, int n_in,
                              void* d_out, int out_size)
{
    const float* h_r  = (const float*)d_in[0];  // (256, 512, 196)
    const float* vecs = (const float*)d_in[1];  // (1000, 300)
    const float* w_g  = (const float*)d_in[2];  // (300, 512)
    float* out = (float*)d_out;                 // (256, 1000, 512)

    cudaFuncSetAttribute(fused_mma, cudaFuncAttributeMaxDynamicSharedMemorySize, SMEM_REQ);

    qgemm16<<<dim3(4, NIPAD / 8), 128>>>(vecs, w_g);
    hsplit<<<dim3(7, 16, NB), dim3(32, 8)>>>(h_r);
    fused_mma<<<dim3(NIPAD / 128, NB), 256, SMEM_REQ>>>(out);
}

// round 12
// speedup vs baseline: 1.8691x; 1.3354x over previous
#include <cuda_runtime.h>
#include <cuda_fp16.h>
#include <cstdint>
#include <math.h>

#define FD 512
#define RD 196
#define RP 224
#define VDIM 300
#define NI 1000
#define NIPAD 1024
#define NB 256

// ---- gemm1sel smem map ----
#define G1_STAGE 28160          // per-stage: QH 128x80B @0, BH 224x80B @10240
#define G1_BH    10240
#define REDM_OFF 56320          // 128 rows x 4 floats
#define SMEM_REQ1 58368

__device__ __align__(16) __half g_qh[NIPAD * FD];                 // q hi (GEMM1 A)
__device__ __align__(16) float  g_q32[NIPAD * FD];                // q fp32 (exact dot)
__device__ __align__(16) __half g_th[(size_t)NB * RP * FD];       // Ht hi [b][r][f] (GEMM1 B)
__device__ __align__(16) float  g_tf[(size_t)NB * RP * FD];       // Ht fp32 [b][r][f] (gather)
__device__ __align__(16) unsigned long long g_mask[(size_t)NB * NIPAD * 4];  // 56-bit chunks

// ---------------- PTX helpers ----------------
__device__ __forceinline__ uint32_t smem_u32(const void* p) {
    uint32_t a;
    asm("{ .reg .u64 t; cvta.to.shared.u64 t, %1; cvt.u32.u64 %0, t; }" : "=r"(a) : "l"(p));
    return a;
}
__device__ __forceinline__ void cpa16(uint32_t d, const void* s) {
    asm volatile("cp.async.cg.shared.global [%0], [%1], 16;" :: "r"(d), "l"(s));
}
#define CP_COMMIT() asm volatile("cp.async.commit_group;")
__device__ __forceinline__ void ldsm4(uint32_t* r, uint32_t a) {
    asm volatile("ldmatrix.sync.aligned.m8n8.x4.shared.b16 {%0,%1,%2,%3},[%4];"
        : "=r"(r[0]), "=r"(r[1]), "=r"(r[2]), "=r"(r[3]) : "r"(a));
}
__device__ __forceinline__ void ldsm2(uint32_t* r, uint32_t a) {
    asm volatile("ldmatrix.sync.aligned.m8n8.x2.shared.b16 {%0,%1},[%2];"
        : "=r"(r[0]), "=r"(r[1]) : "r"(a));
}
__device__ __forceinline__ void mma_f32(float* d, const uint32_t* a, uint32_t b0, uint32_t b1) {
    asm volatile("mma.sync.aligned.m16n8k16.row.col.f32.f16.f16.f32 "
        "{%0,%1,%2,%3},{%4,%5,%6,%7},{%8,%9},{%0,%1,%2,%3};"
        : "+f"(d[0]), "+f"(d[1]), "+f"(d[2]), "+f"(d[3])
        : "r"(a[0]), "r"(a[1]), "r"(a[2]), "r"(a[3]), "r"(b0), "r"(b1));
}

// ---------------- prep 1: q = vecs @ w_g -> fp16 hi + fp32 ----------------
__global__ __launch_bounds__(128) void qgemm16(
    const float* __restrict__ vecs, const float* __restrict__ w_g)
{
    __shared__ float vs[8][VDIM];
    const int f = blockIdx.x * 128 + threadIdx.x;
    const int i0 = blockIdx.y * 8;
    for (int e = threadIdx.x; e < 8 * VDIM; e += 128) {
        int ii = e / VDIM, v = e % VDIM, i = i0 + ii;
        vs[ii][v] = (i < NI) ? vecs[i * VDIM + v] : 0.0f;
    }
    __syncthreads();
    float acc[8];
#pragma unroll
    for (int ii = 0; ii < 8; ii++) acc[ii] = 0.0f;
#pragma unroll 4
    for (int v = 0; v < VDIM; v++) {
        float w = w_g[v * FD + f];
#pragma unroll
        for (int ii = 0; ii < 8; ii++) acc[ii] += vs[ii][v] * w;
    }
#pragma unroll
    for (int ii = 0; ii < 8; ii++) {
        size_t o = (size_t)(i0 + ii) * FD + f;
        g_qh[o] = __float2half_rn(acc[ii]);
        g_q32[o] = acc[ii];
    }
}

// ---------------- prep 2: transpose H -> g_th (hi) + g_tf (fp32) ----------------
__global__ __launch_bounds__(256) void hsplit(const float* __restrict__ h)
{
    __shared__ float t[32][33];
    const int b = blockIdx.z, f0 = blockIdx.y * 32, r0 = blockIdx.x * 32;
    const int tx = threadIdx.x, ty = threadIdx.y;
#pragma unroll
    for (int s = 0; s < 4; s++) {
        int fl = ty + 8 * s, r = r0 + tx;
        t[fl][tx] = (r < RD) ? h[((size_t)b * FD + f0 + fl) * RD + r] : 0.0f;
    }
    __syncthreads();
#pragma unroll
    for (int s = 0; s < 4; s++) {
        int rl = ty + 8 * s;
        float v = t[tx][rl];
        size_t o = ((size_t)b * RP + r0 + rl) * FD + f0 + tx;
        g_th[o] = __float2half_rn(v);
        g_tf[o] = v;
    }
}

// ---------------- GEMM1 stage loader (hi only) ----------------
__device__ __forceinline__ void issue_g1(uint32_t sb,
    const __half* qh, const __half* th, int c, int tid)
{
    const int ko = c * 32;
    for (int t = tid; t < 512; t += 256) {
        int row = t >> 2, cc = t & 3;
        cpa16(sb + row * 80 + cc * 16, qh + row * FD + ko + cc * 8);
    }
    for (int t = tid; t < 896; t += 256) {
        int row = t >> 2, cc = t & 3;
        cpa16(sb + G1_BH + row * 80 + cc * 16, th + row * FD + ko + cc * 8);
    }
}

// ---------------- kernel 3: GEMM1 (hi only) + candidate mask epilogue ----------------
__global__ __launch_bounds__(256) void gemm1sel()
{
    extern __shared__ char sm[];
    const uint32_t sbase = smem_u32(sm);
    float* redm = reinterpret_cast<float*>(sm + REDM_OFF);

    const int tid = threadIdx.x, lane = tid & 31, wid = tid >> 5;
    const int mw = wid >> 2, nw = wid & 3;
    const int b = blockIdx.y, i0 = blockIdx.x * 128;

    const __half* qh = g_qh + (size_t)i0 * FD;
    const __half* th = g_th + (size_t)b * RP * FD;

    const int arow = (lane & 7) + ((lane >> 3) & 1) * 8;
    const int acg  = (lane >> 4) * 16;

    float acc[4][7][4];
#pragma unroll
    for (int mf = 0; mf < 4; mf++)
#pragma unroll
        for (int nf = 0; nf < 7; nf++)
#pragma unroll
            for (int e = 0; e < 4; e++) acc[mf][nf][e] = 0.0f;

    issue_g1(sbase, qh, th, 0, tid);
    CP_COMMIT();
    for (int c = 0; c < 16; c++) {
        const uint32_t st = sbase + (uint32_t)(c & 1) * G1_STAGE;
        if (c < 15) {
            issue_g1(sbase + (uint32_t)((c + 1) & 1) * G1_STAGE, qh, th, c + 1, tid);
            CP_COMMIT();
            asm volatile("cp.async.wait_group 1;");
        } else {
            asm volatile("cp.async.wait_group 0;");
        }
        __syncthreads();
#pragma unroll
        for (int kk = 0; kk < 2; kk++) {
            uint32_t ah[4][4];
#pragma unroll
            for (int mf = 0; mf < 4; mf++) {
                uint32_t ad = st + (uint32_t)(mw * 64 + mf * 16 + arow) * 80 + kk * 32 + acg;
                ldsm4(ah[mf], ad);
            }
#pragma unroll
            for (int p = 0; p < 3; p++) {
                uint32_t bd = st + G1_BH + (uint32_t)(nw * 56 + p * 16 + arow) * 80 + kk * 32 + acg;
                uint32_t bh[4];
                ldsm4(bh, bd);
#pragma unroll
                for (int mf = 0; mf < 4; mf++) {
                    mma_f32(acc[mf][2 * p],     ah[mf], bh[0], bh[2]);
                    mma_f32(acc[mf][2 * p + 1], ah[mf], bh[1], bh[3]);
                }
            }
            {
                uint32_t bd = st + G1_BH + (uint32_t)(nw * 56 + 48 + (lane & 7)) * 80
                              + kk * 32 + ((lane >> 3) & 1) * 16;
                uint32_t bh[2];
                ldsm2(bh, bd);
#pragma unroll
                for (int mf = 0; mf < 4; mf++)
                    mma_f32(acc[mf][6], ah[mf], bh[0], bh[1]);
            }
        }
        __syncthreads();
    }

    // ---- epilogue: per-row max (cross-warp) then 56-bit candidate mask ----
    const int qlane = lane >> 2, plane = 2 * (lane & 3);
#pragma unroll
    for (int mf = 0; mf < 4; mf++)
#pragma unroll
        for (int hh = 0; hh < 2; hh++) {
            float mx = -INFINITY;
#pragma unroll
            for (int nf = 0; nf < 7; nf++)
#pragma unroll
                for (int e = 0; e < 2; e++) {
                    int col = nw * 56 + nf * 8 + plane + e;
                    if (col < RD) mx = fmaxf(mx, acc[mf][nf][2 * hh + e]);
                }
            mx = fmaxf(mx, __shfl_xor_sync(0xffffffffu, mx, 1));
            mx = fmaxf(mx, __shfl_xor_sync(0xffffffffu, mx, 2));
            if ((lane & 3) == 0) {
                int row = mw * 64 + mf * 16 + qlane + hh * 8;
                redm[row * 4 + nw] = mx;
            }
        }
    __syncthreads();
#pragma unroll
    for (int mf = 0; mf < 4; mf++)
#pragma unroll
        for (int hh = 0; hh < 2; hh++) {
            int row = mw * 64 + mf * 16 + qlane + hh * 8;
            float M = fmaxf(fmaxf(redm[row * 4], redm[row * 4 + 1]),
                            fmaxf(redm[row * 4 + 2], redm[row * 4 + 3]));
            float thr = M - 22.0f;
            unsigned long long mb = 0ull;
#pragma unroll
            for (int nf = 0; nf < 7; nf++)
#pragma unroll
                for (int e = 0; e < 2; e++) {
                    int col = nw * 56 + nf * 8 + plane + e;
                    if (col < RD && acc[mf][nf][2 * hh + e] > thr)
                        mb |= 1ull << (nf * 8 + plane + e);
                }
            mb |= __shfl_xor_sync(0xffffffffu, mb, 1);
            mb |= __shfl_xor_sync(0xffffffffu, mb, 2);
            if ((lane & 3) == 0)
                g_mask[((size_t)b * NIPAD + i0 + row) * 4 + nw] = mb;
        }
}

// ---------------- kernel 4: high-occupancy exact softmax-gather ----------------
// grid (125, 256), 256 threads: one warp per (b, i) row
__global__ __launch_bounds__(256) void gather(float* __restrict__ out)
{
    const int lane = threadIdx.x & 31, wid = threadIdx.x >> 5;
    const int b = blockIdx.y;
    const int i = blockIdx.x * 8 + wid;          // 125*8 = 1000 exactly

    const size_t gr = (size_t)b * NIPAD + i;
    const float* q32 = g_q32 + (size_t)i * FD;
    float qr[16];
#pragma unroll
    for (int k = 0; k < 16; k++) qr[k] = q32[lane + 32 * k];

    float m = -INFINITY, ssum = 0.0f;
    float eg[16];
#pragma unroll
    for (int k = 0; k < 16; k++) eg[k] = 0.0f;

#pragma unroll 1
    for (int j = 0; j < 4; j++) {
        unsigned long long bs = g_mask[gr * 4 + j];
        while (bs) {
            int p = __ffsll(bs) - 1; bs &= bs - 1;
            int c = j * 56 + p;
            const float* hp = g_tf + ((size_t)b * RP + c) * FD;
            float hr[16];
#pragma unroll
            for (int k = 0; k < 16; k++) hr[k] = hp[lane + 32 * k];
            float s = 0.0f;
#pragma unroll
            for (int k = 0; k < 16; k++) s += qr[k] * hr[k];
#pragma unroll
            for (int o = 16; o > 0; o >>= 1) s += __shfl_xor_sync(0xffffffffu, s, o);
            float mn = fmaxf(m, s);
            float sc = __expf(m - mn);
            float w  = __expf(s - mn);
            ssum = ssum * sc + w;
#pragma unroll
            for (int k = 0; k < 16; k++) eg[k] = eg[k] * sc + w * hr[k];
            m = mn;
        }
    }
    const float inv = 1.0f / ssum;
    float* op = out + ((size_t)b * NI + i) * FD;
#pragma unroll
    for (int k = 0; k < 16; k++) op[lane + 32 * k] = eg[k] * inv;
}

// ---------------------------------------------------------------------------
extern "C" void kernel_launch(void* const* d_in, const int* in_sizes, int n_in,
                              void* d_out, int out_size)
{
    const float* h_r  = (const float*)d_in[0];  // (256, 512, 196)
    const float* vecs = (const float*)d_in[1];  // (1000, 300)
    const float* w_g  = (const float*)d_in[2];  // (300, 512)
    float* out = (float*)d_out;                 // (256, 1000, 512)

    cudaFuncSetAttribute(gemm1sel, cudaFuncAttributeMaxDynamicSharedMemorySize, SMEM_REQ1);

    qgemm16<<<dim3(4, NIPAD / 8), 128>>>(vecs, w_g);
    hsplit<<<dim3(7, 16, NB), dim3(32, 8)>>>(h_r);
    gemm1sel<<<dim3(NIPAD / 128, NB), 256, SMEM_REQ1>>>();
    gather<<<dim3(125, NB), 256>>>(out);
}